// round 3
// baseline (speedup 1.0000x reference)
#include <cuda_runtime.h>
#include <cstdint>

// ---- problem constants ----
#define BSZ 8
#define SEQLEN 16
#define DIM 4096
#define NH 32
#define NKV 8
#define HD 128
#define CACHE 4096
#define M_TOT 128
#define QKV_N 6144
#define CACHE_PER_B 4194304L // 4096*8*128
#define CK_OFF 524288L
#define CV_OFF 34078720L
#define INV_SQRT_HD 0.08838834764831845f
#define TSPLIT 8

// ---- scratch ----
__device__ float g_qkv_part[4][M_TOT * QKV_N];   // split-K partials of QKV proj
__device__ float g_xq[64 * 64 * 128];            // rope'd q, [pair][row][d]
__device__ float g_opart[64 * TSPLIT * 64 * 128];// flash partial O
__device__ float2 g_ml[64 * TSPLIT * 64];        // flash partial (m, l)
__device__ float g_attn[M_TOT * 4096];           // [b*16+q][h*128+d]
__device__ float g_out_part[4][M_TOT * DIM];     // split-K partials of out proj

// ---- helpers ----
__device__ __forceinline__ uint32_t f2tf(float f) {
    uint32_t u;
    asm("cvt.rna.tf32.f32 %0, %1;" : "=r"(u) : "f"(f));
    return u;
}

__device__ __forceinline__ void mma_tf32(float (&d)[4], const uint32_t (&a)[4],
                                         const uint32_t (&b)[2]) {
    asm volatile(
        "mma.sync.aligned.m16n8k8.row.col.f32.tf32.tf32.f32 "
        "{%0,%1,%2,%3}, {%4,%5,%6,%7}, {%8,%9}, {%0,%1,%2,%3};\n"
        : "+f"(d[0]), "+f"(d[1]), "+f"(d[2]), "+f"(d[3])
        : "r"(a[0]), "r"(a[1]), "r"(a[2]), "r"(a[3]), "r"(b[0]), "r"(b[1]));
}

// ================= cache shift =================
__global__ void shift_caches(const float4* __restrict__ ck,
                             const float4* __restrict__ cv,
                             float4* __restrict__ out) {
    long i = (long)blockIdx.x * 256 + threadIdx.x;
    const long PER = 8L * 4080 * 256;
    if (i < PER) {
        long b = i / (4080L * 256), r = i - b * (4080L * 256);
        out[CK_OFF / 4 + b * 1048576 + r] = ck[b * 1048576 + 4096 + r];
    } else if (i < 2 * PER) {
        long j = i - PER;
        long b = j / (4080L * 256), r = j - b * (4080L * 256);
        out[CV_OFF / 4 + b * 1048576 + r] = cv[b * 1048576 + 4096 + r];
    }
}

// ================= generic tf32 mma core: C += A(row,[M][K]) * B(row,[N][K])^T ==========
template <int MF>
__device__ __forceinline__ void gemm_abt_core(const float* __restrict__ A, long lda,
                                              const float* __restrict__ B, long ldb,
                                              int ktiles, uint32_t* As, uint32_t* Bs,
                                              float (&acc)[MF][4][4]) {
    const int tid = threadIdx.x;
    const int lane = tid & 31, wid = tid >> 5;
    const int wm = wid >> 2, wn = wid & 3;
    const int g = lane >> 2, tig = lane & 3;

    for (int t = 0; t < ktiles; t++) {
        const float* Ak = A + t * 16;
        const float* Bk = B + t * 16;
#pragma unroll
        for (int i = 0; i < MF / 2; i++) {
            int v = tid + i * 256;
            int r = v >> 2, c4 = v & 3;
            float4 x = *(const float4*)(Ak + (long)r * lda + c4 * 4);
            uint4 y = make_uint4(f2tf(x.x), f2tf(x.y), f2tf(x.z), f2tf(x.w));
            *(uint4*)(As + r * 20 + c4 * 4) = y;
        }
#pragma unroll
        for (int i = 0; i < 2; i++) {
            int v = tid + i * 256;
            int r = v >> 2, c4 = v & 3;
            float4 x = *(const float4*)(Bk + (long)r * ldb + c4 * 4);
            uint4 y = make_uint4(f2tf(x.x), f2tf(x.y), f2tf(x.z), f2tf(x.w));
            *(uint4*)(Bs + r * 20 + c4 * 4) = y;
        }
        __syncthreads();
#pragma unroll
        for (int ks = 0; ks < 16; ks += 8) {
            uint32_t a[MF][4], b[4][2];
#pragma unroll
            for (int mf = 0; mf < MF; mf++) {
                int m = wm * (MF * 16) + mf * 16;
                a[mf][0] = As[(m + g) * 20 + ks + tig];
                a[mf][1] = As[(m + g + 8) * 20 + ks + tig];
                a[mf][2] = As[(m + g) * 20 + ks + tig + 4];
                a[mf][3] = As[(m + g + 8) * 20 + ks + tig + 4];
            }
#pragma unroll
            for (int nf = 0; nf < 4; nf++) {
                int n = wn * 32 + nf * 8 + g;
                b[nf][0] = Bs[n * 20 + ks + tig];
                b[nf][1] = Bs[n * 20 + ks + tig + 4];
            }
#pragma unroll
            for (int mf = 0; mf < MF; mf++)
#pragma unroll
                for (int nf = 0; nf < 4; nf++) mma_tf32(acc[mf][nf], a[mf], b[nf]);
        }
        __syncthreads();
    }
}

template <int MF>
__device__ __forceinline__ void store_acc(float* __restrict__ C, long ldc,
                                          float (&acc)[MF][4][4]) {
    const int tid = threadIdx.x;
    const int lane = tid & 31, wid = tid >> 5;
    const int wm = wid >> 2, wn = wid & 3;
    const int g = lane >> 2, tig = lane & 3;
#pragma unroll
    for (int mf = 0; mf < MF; mf++) {
        int m = wm * (MF * 16) + mf * 16 + g;
#pragma unroll
        for (int nf = 0; nf < 4; nf++) {
            int n = wn * 32 + nf * 8 + 2 * tig;
            *(float2*)(C + (long)m * ldc + n) = make_float2(acc[mf][nf][0], acc[mf][nf][1]);
            *(float2*)(C + (long)(m + 8) * ldc + n) = make_float2(acc[mf][nf][2], acc[mf][nf][3]);
        }
    }
}

// ================= QKV projection (split-K=4) =================
__global__ void qkv_gemm_t(const float* __restrict__ X, const float* __restrict__ wq,
                           const float* __restrict__ wk, const float* __restrict__ wv) {
    __shared__ uint32_t As[128 * 20], Bs[128 * 20];
    int n0 = blockIdx.x * 128, split = blockIdx.y;
    const float* W;
    int nl;
    if (n0 < 4096) { W = wq; nl = n0; }
    else if (n0 < 5120) { W = wk; nl = n0 - 4096; }
    else { W = wv; nl = n0 - 5120; }
    float acc[4][4][4] = {};
    gemm_abt_core<4>(X + split * 1024, 4096, W + (long)nl * 4096 + split * 1024, 4096, 64,
                     As, Bs, acc);
    store_acc<4>(g_qkv_part[split] + n0, QKV_N, acc);
}

// ================= RoPE + split reduce + scatter K/V =================
__global__ void rope_scatter(const float* __restrict__ freqs, float* __restrict__ out) {
    int m = blockIdx.x;  // 0..127
    int b = m >> 4, s = m & 15;
    long base = (long)m * QKV_N;
#pragma unroll 1
    for (int p = threadIdx.x; p < 2048; p += 256) {
        int h = p >> 6, i = p & 63;
        float re = g_qkv_part[0][base + 2 * p] + g_qkv_part[1][base + 2 * p] +
                   g_qkv_part[2][base + 2 * p] + g_qkv_part[3][base + 2 * p];
        float im = g_qkv_part[0][base + 2 * p + 1] + g_qkv_part[1][base + 2 * p + 1] +
                   g_qkv_part[2][base + 2 * p + 1] + g_qkv_part[3][base + 2 * p + 1];
        float c = freqs[(s * 64 + i) * 2], sn = freqs[(s * 64 + i) * 2 + 1];
        long d = ((long)(b * 32 + h) * 16 + s) * 128 + 2 * i;
        g_xq[d] = re * c - im * sn;
        g_xq[d + 1] = re * sn + im * c;
    }
    float* ck = out + CK_OFF + (long)b * CACHE_PER_B + (long)(4080 + s) * 1024;
#pragma unroll 1
    for (int p = threadIdx.x; p < 512; p += 256) {
        int i = p & 63;
        long o = base + 4096 + 2 * p;
        float re = g_qkv_part[0][o] + g_qkv_part[1][o] + g_qkv_part[2][o] + g_qkv_part[3][o];
        float im = g_qkv_part[0][o + 1] + g_qkv_part[1][o + 1] + g_qkv_part[2][o + 1] +
                   g_qkv_part[3][o + 1];
        float c = freqs[(s * 64 + i) * 2], sn = freqs[(s * 64 + i) * 2 + 1];
        ck[2 * p] = re * c - im * sn;
        ck[2 * p + 1] = re * sn + im * c;
    }
    float* cv = out + CV_OFF + (long)b * CACHE_PER_B + (long)(4080 + s) * 1024;
#pragma unroll 1
    for (int j = threadIdx.x; j < 1024; j += 256) {
        long o = base + 5120 + j;
        cv[j] = g_qkv_part[0][o] + g_qkv_part[1][o] + g_qkv_part[2][o] + g_qkv_part[3][o];
    }
}

// ================= fused flash attention =================
// grid (64 pairs, 8 tsplits), 128 threads = 4 warps; warp owns 16 rows.
__global__ void __launch_bounds__(128, 2)
flash_attn(const float* __restrict__ ck, const float* __restrict__ cv,
           const float* __restrict__ mask) {
    extern __shared__ uint32_t sh[];
    uint32_t* Ks = sh;               // 64 x 132
    uint32_t* Vs = sh + 64 * 132;    // 64 x 132
    int pair = blockIdx.x, ts = blockIdx.y;
    int b = pair >> 3, kv = pair & 7;
    int tid = threadIdx.x, lane = tid & 31, w = tid >> 5;
    int g = lane >> 2, tig = lane & 3;

    // Q fragments -> registers (once)
    const float* Q = g_xq + (long)pair * 8192 + (long)w * 16 * 128;
    uint32_t aq[16][4];
#pragma unroll
    for (int ks = 0; ks < 16; ks++) {
        aq[ks][0] = f2tf(Q[g * 128 + ks * 8 + tig]);
        aq[ks][1] = f2tf(Q[(g + 8) * 128 + ks * 8 + tig]);
        aq[ks][2] = f2tf(Q[g * 128 + ks * 8 + tig + 4]);
        aq[ks][3] = f2tf(Q[(g + 8) * 128 + ks * 8 + tig + 4]);
    }
    float o[16][4] = {};
    float m_lo = -1e30f, m_hi = -1e30f, l_lo = 0.f, l_hi = 0.f;

    const float* Kbase = ck + (long)b * CACHE_PER_B + kv * 128;
    const float* Vbase = cv + (long)b * CACHE_PER_B + kv * 128;
    int r = tid >> 1, half = tid & 1;

    for (int c = 0; c < 8; c++) {
        int t0 = ts * 512 + c * 64;
        const float* kr = Kbase + (long)(t0 + r) * 1024 + half * 64;
        const float* vr = Vbase + (long)(t0 + r) * 1024 + half * 64;
#pragma unroll
        for (int i = 0; i < 16; i++) {
            float4 x = *(const float4*)(kr + i * 4);
            *(uint4*)&Ks[r * 132 + half * 64 + i * 4] =
                make_uint4(f2tf(x.x), f2tf(x.y), f2tf(x.z), f2tf(x.w));
            float4 y = *(const float4*)(vr + i * 4);
            *(uint4*)&Vs[r * 132 + half * 64 + i * 4] =
                make_uint4(f2tf(y.x), f2tf(y.y), f2tf(y.z), f2tf(y.w));
        }
        __syncthreads();

        // S = Q K^T (16 x 64 per warp)
        float s[8][4] = {};
#pragma unroll
        for (int ks = 0; ks < 16; ks++) {
#pragma unroll
            for (int nf = 0; nf < 8; nf++) {
                uint32_t b2[2];
                b2[0] = Ks[(nf * 8 + g) * 132 + ks * 8 + tig];
                b2[1] = Ks[(nf * 8 + g) * 132 + ks * 8 + tig + 4];
                mma_tf32(s[nf], aq[ks], b2);
            }
        }

        // scale + mask + online softmax (rows g and g+8, warp-local)
        float mx_lo = -1e30f, mx_hi = -1e30f;
#pragma unroll
        for (int nf = 0; nf < 8; nf++) {
            int t = t0 + nf * 8 + 2 * tig;
            float2 mk0 = *(const float2*)&mask[g * 4096 + t];
            float2 mk1 = *(const float2*)&mask[(g + 8) * 4096 + t];
            s[nf][0] = s[nf][0] * INV_SQRT_HD + mk0.x;
            s[nf][1] = s[nf][1] * INV_SQRT_HD + mk0.y;
            s[nf][2] = s[nf][2] * INV_SQRT_HD + mk1.x;
            s[nf][3] = s[nf][3] * INV_SQRT_HD + mk1.y;
            mx_lo = fmaxf(mx_lo, fmaxf(s[nf][0], s[nf][1]));
            mx_hi = fmaxf(mx_hi, fmaxf(s[nf][2], s[nf][3]));
        }
        mx_lo = fmaxf(mx_lo, __shfl_xor_sync(0xffffffffu, mx_lo, 1));
        mx_lo = fmaxf(mx_lo, __shfl_xor_sync(0xffffffffu, mx_lo, 2));
        mx_hi = fmaxf(mx_hi, __shfl_xor_sync(0xffffffffu, mx_hi, 1));
        mx_hi = fmaxf(mx_hi, __shfl_xor_sync(0xffffffffu, mx_hi, 2));
        float mn_lo = fmaxf(m_lo, mx_lo), mn_hi = fmaxf(m_hi, mx_hi);
        float al_lo = __expf(m_lo - mn_lo), al_hi = __expf(m_hi - mn_hi);
        m_lo = mn_lo; m_hi = mn_hi;
        float sum_lo = 0.f, sum_hi = 0.f;
#pragma unroll
        for (int nf = 0; nf < 8; nf++) {
            s[nf][0] = __expf(s[nf][0] - m_lo);
            s[nf][1] = __expf(s[nf][1] - m_lo);
            s[nf][2] = __expf(s[nf][2] - m_hi);
            s[nf][3] = __expf(s[nf][3] - m_hi);
            sum_lo += s[nf][0] + s[nf][1];
            sum_hi += s[nf][2] + s[nf][3];
        }
        sum_lo += __shfl_xor_sync(0xffffffffu, sum_lo, 1);
        sum_lo += __shfl_xor_sync(0xffffffffu, sum_lo, 2);
        sum_hi += __shfl_xor_sync(0xffffffffu, sum_hi, 1);
        sum_hi += __shfl_xor_sync(0xffffffffu, sum_hi, 2);
        l_lo = l_lo * al_lo + sum_lo;
        l_hi = l_hi * al_hi + sum_hi;
#pragma unroll
        for (int nf = 0; nf < 16; nf++) {
            o[nf][0] *= al_lo; o[nf][1] *= al_lo;
            o[nf][2] *= al_hi; o[nf][3] *= al_hi;
        }

        __syncthreads();  // all warps done reading Ks

        // P -> smem (reuse Ks region), stride 68, warp-local rows
        uint32_t* Ps = Ks;
#pragma unroll
        for (int nf = 0; nf < 8; nf++) {
            int colb = nf * 8 + 2 * tig;
            Ps[(w * 16 + g) * 68 + colb]         = f2tf(s[nf][0]);
            Ps[(w * 16 + g) * 68 + colb + 1]     = f2tf(s[nf][1]);
            Ps[(w * 16 + g + 8) * 68 + colb]     = f2tf(s[nf][2]);
            Ps[(w * 16 + g + 8) * 68 + colb + 1] = f2tf(s[nf][3]);
        }
        __syncwarp();

        // O += P V  (k = t, 8 k-blocks)
#pragma unroll
        for (int ks = 0; ks < 8; ks++) {
            uint32_t a[4];
            a[0] = Ps[(w * 16 + g) * 68 + ks * 8 + tig];
            a[1] = Ps[(w * 16 + g + 8) * 68 + ks * 8 + tig];
            a[2] = Ps[(w * 16 + g) * 68 + ks * 8 + tig + 4];
            a[3] = Ps[(w * 16 + g + 8) * 68 + ks * 8 + tig + 4];
#pragma unroll
            for (int nf = 0; nf < 16; nf++) {
                uint32_t b2[2];
                b2[0] = Vs[(ks * 8 + tig) * 132 + nf * 8 + g];
                b2[1] = Vs[(ks * 8 + tig + 4) * 132 + nf * 8 + g];
                mma_tf32(o[nf], a, b2);
            }
        }
        __syncthreads();  // before next chunk overwrites Ks/Vs
    }

    // epilogue: unnormalized O + (m,l)
    float* Op = g_opart + ((long)(pair * TSPLIT + ts) * 64 + w * 16) * 128;
#pragma unroll
    for (int nf = 0; nf < 16; nf++) {
        int d = nf * 8 + 2 * tig;
        *(float2*)&Op[g * 128 + d] = make_float2(o[nf][0], o[nf][1]);
        *(float2*)&Op[(g + 8) * 128 + d] = make_float2(o[nf][2], o[nf][3]);
    }
    if (tig == 0) {
        g_ml[(pair * TSPLIT + ts) * 64 + w * 16 + g] = make_float2(m_lo, l_lo);
        g_ml[(pair * TSPLIT + ts) * 64 + w * 16 + g + 8] = make_float2(m_hi, l_hi);
    }
}

// ================= flash combine (LSE merge of 8 splits) =================
__global__ void flash_combine() {
    int row = blockIdx.x;  // pair*64 + r
    int pair = row >> 6, r = row & 63;
    int b = pair >> 3, kv = pair & 7;
    int hl = r >> 4, q = r & 15;
    int d = threadIdx.x;  // 0..127
    float2 ml[TSPLIT];
    float M = -1e30f;
#pragma unroll
    for (int ts = 0; ts < TSPLIT; ts++) {
        ml[ts] = g_ml[(pair * TSPLIT + ts) * 64 + r];
        M = fmaxf(M, ml[ts].x);
    }
    float L = 0.f, acc = 0.f;
#pragma unroll
    for (int ts = 0; ts < TSPLIT; ts++) {
        float wgt = __expf(ml[ts].x - M);
        L += ml[ts].y * wgt;
        acc += wgt * g_opart[((long)(pair * TSPLIT + ts) * 64 + r) * 128 + d];
    }
    g_attn[((long)(b * 16 + q) * 4096) + (kv * 4 + hl) * 128 + d] = acc / L;
}

// ================= out = attn @ wo^T (split-K=4) =================
__global__ void out_gemm_t(const float* __restrict__ wo) {
    __shared__ uint32_t As[128 * 20], Bs[128 * 20];
    int n0 = blockIdx.x * 128, split = blockIdx.y;
    float acc[4][4][4] = {};
    gemm_abt_core<4>(g_attn + split * 1024, 4096, wo + (long)n0 * 4096 + split * 1024, 4096,
                     64, As, Bs, acc);
    store_acc<4>(g_out_part[split] + n0, 4096, acc);
}

__global__ void out_reduce(float* __restrict__ out) {
    long idx = (long)blockIdx.x * 256 + threadIdx.x;
    float4 p0 = ((const float4*)g_out_part[0])[idx];
    float4 p1 = ((const float4*)g_out_part[1])[idx];
    float4 p2 = ((const float4*)g_out_part[2])[idx];
    float4 p3 = ((const float4*)g_out_part[3])[idx];
    ((float4*)out)[idx] = make_float4(p0.x + p1.x + p2.x + p3.x, p0.y + p1.y + p2.y + p3.y,
                                      p0.z + p1.z + p2.z + p3.z, p0.w + p1.w + p2.w + p3.w);
}

// ================= launch =================
extern "C" void kernel_launch(void* const* d_in, const int* in_sizes, int n_in,
                              void* d_out, int out_size) {
    const float* x     = (const float*)d_in[0];
    const float* mask  = (const float*)d_in[1];
    const float* freqs = (const float*)d_in[2];
    const float* ck    = (const float*)d_in[3];
    const float* cv    = (const float*)d_in[4];
    const float* wq    = (const float*)d_in[5];
    const float* wk    = (const float*)d_in[6];
    const float* wv    = (const float*)d_in[7];
    const float* wo    = (const float*)d_in[8];
    float* out = (float*)d_out;

    static int smem_set = 0;
    if (!smem_set) {
        cudaFuncSetAttribute(flash_attn, cudaFuncAttributeMaxDynamicSharedMemorySize,
                             2 * 64 * 132 * 4);
        smem_set = 1;
    }

    shift_caches<<<65280, 256>>>((const float4*)ck, (const float4*)cv, (float4*)out);
    qkv_gemm_t<<<dim3(48, 4), 256>>>(x, wq, wk, wv);
    rope_scatter<<<128, 256>>>(freqs, out);
    flash_attn<<<dim3(64, TSPLIT), 128, 2 * 64 * 132 * 4>>>(out + CK_OFF, out + CV_OFF, mask);
    flash_combine<<<4096, 128>>>();
    out_gemm_t<<<dim3(32, 4), 256>>>(wo);
    out_reduce<<<512, 256>>>(out);
}